// round 6
// baseline (speedup 1.0000x reference)
#include <cuda_runtime.h>
#include <cstdint>

// Problem constants
#define NB   32
#define CIN  256
#define COUT 256
#define H    56
#define W    56
#define HB   58   // padded rows (0..57)
#define WB   66   // padded cols (0..65; cols >57 always zero)

// e4m3 encodings of sign values
#define FP8_P1 0x38
#define FP8_M1 0xB8

// conv staging: stage covers 128 ci: A = 128px x 128B, B = 128co x 128B
#define STG_A   16384
#define STG_SZ  32768
#define NSTAGE  3
#define SMEM_EPI_OFF 1024
#define SMEM_BUF_OFF 1024
#define SMEM_TOTAL   (1024 + NSTAGE * STG_SZ)   // 99328

// Scratch (e4m3 bytes: +-1/0 exact)
__device__ __align__(1024) uint8_t g_act[(size_t)NB * HB * WB * CIN];
__device__ __align__(1024) uint8_t g_wb[9 * COUT * CIN];

__device__ __forceinline__ uint8_t f8sign(float v) {
    return (v > 0.f) ? (uint8_t)FP8_P1 : ((v < 0.f) ? (uint8_t)FP8_M1 : (uint8_t)0);
}

__device__ __forceinline__ uint32_t su32(const void* p) {
    return (uint32_t)__cvta_generic_to_shared(p);
}

#define CP16(dst, src) \
    asm volatile("cp.async.cg.shared.global [%0], [%1], 16;\n" :: "r"(dst), "l"(src))
#define CP_COMMIT() asm volatile("cp.async.commit_group;\n" ::: "memory")
#define CP_WAIT1()  asm volatile("cp.async.wait_group 1;\n" ::: "memory")

__device__ __forceinline__ void ldsm_x4(uint32_t* r, uint32_t addr) {
    asm volatile("ldmatrix.sync.aligned.m8n8.x4.shared.b16 {%0,%1,%2,%3}, [%4];"
                 : "=r"(r[0]), "=r"(r[1]), "=r"(r[2]), "=r"(r[3]) : "r"(addr));
}
// FP8 e4m3 MMA, f32 accumulate. Fragment layout identical to s8 m16n8k32
// (validated rel_err=0 in rounds 3-4).
__device__ __forceinline__ void mma_f8(float* d, const uint32_t* a, const uint32_t* b) {
    asm volatile(
        "mma.sync.aligned.m16n8k32.row.col.f32.e4m3.e4m3.f32 "
        "{%0,%1,%2,%3}, {%4,%5,%6,%7}, {%8,%9}, {%0,%1,%2,%3};\n"
        : "+f"(d[0]), "+f"(d[1]), "+f"(d[2]), "+f"(d[3])
        : "r"(a[0]), "r"(a[1]), "r"(a[2]), "r"(a[3]), "r"(b[0]), "r"(b[1]));
}

// ---------------------------------------------------------------------------
// Binarize + transpose x: NCHW fp32 -> padded NHWC e4m3 (interior only).
// ---------------------------------------------------------------------------
__global__ void bin_act_kernel(const float* __restrict__ x) {
    __shared__ uint8_t t[32][33];
    int nz = blockIdx.z;
    int n = nz / H, y = nz % H;
    int x0 = blockIdx.x * 32;
    int c0 = blockIdx.y * 32;
    int tx = threadIdx.x, ty = threadIdx.y;

    #pragma unroll
    for (int i = 0; i < 4; i++) {
        int ci = c0 + ty + i * 8;
        int xx = x0 + tx;
        float v = 0.f;
        if (xx < W)
            v = x[(((size_t)n * CIN + ci) * H + y) * W + xx];
        t[ty + i * 8][tx] = f8sign(v);
    }
    __syncthreads();
    #pragma unroll
    for (int i = 0; i < 4; i++) {
        int xx = x0 + ty + i * 8;
        if (xx < W) {
            g_act[(((size_t)n * HB + (y + 1)) * WB + (xx + 1)) * CIN + c0 + tx] =
                t[tx][ty + i * 8];
        }
    }
}

__global__ void bin_w_kernel(const float* __restrict__ M) {
    int o = blockIdx.x * 256 + threadIdx.x;
    int tap = o >> 16;
    int co  = (o >> 8) & 255;
    int ci  = o & 255;
    g_wb[o] = f8sign(M[(size_t)(co * CIN + ci) * 9 + tap]);
}

// ---------------------------------------------------------------------------
// FP8 implicit-GEMM conv. CTA: 128 px (4y x 32x) x 128 co; K = 9*256.
// 18 stages of 128 ci; 3-buffer cp.async pipeline; ldmatrix + mma.m16n8k32.e4m3.
// ---------------------------------------------------------------------------
__global__ void __launch_bounds__(256, 2)
conv_mma_kernel(const float* __restrict__ alpha, float* __restrict__ out) {
    extern __shared__ char smem[];
    uint32_t sb = su32(smem);
    float* alphaS = (float*)smem;                 // 512B
    float* epi    = (float*)(smem + SMEM_EPI_OFF);

    int tid  = threadIdx.x;
    int wid  = tid >> 5, lane = tid & 31;
    int bx   = blockIdx.x;                        // 0..27
    int xt   = bx & 1, yt = bx >> 1;
    int x0   = xt * 32, y0 = yt * 4;
    int n    = blockIdx.y;
    int co0  = blockIdx.z * 128;

    if (tid < 128) alphaS[tid] = alpha[co0 + tid];

    // ---- producer constants ----
    int pc = tid & 7;            // 16B chunk within 128B row (16 ci each)
    int pr = tid >> 3;           // row 0..31
    uint32_t pdst = (uint32_t)(pr * 128) + (uint32_t)(((pc ^ (pr & 7)) << 4));
    const uint8_t* gaBase =
        g_act + ((size_t)(n * HB + y0) * WB + (x0 + pr)) * CIN + pc * 16;
    const uint8_t* gbBase = g_wb + (size_t)(co0 + pr) * CIN + pc * 16;

    auto produce = [&](int s) {
        if (s < 18) {
            int tap = s >> 1, half = s & 1;      // 128-ci half
            int kh = tap / 3, kw = tap - kh * 3;
            const uint8_t* ga = gaBase + ((kh * WB + kw) * CIN + half * 128);
            const uint8_t* gb = gbBase + ((size_t)tap * (COUT * CIN) + half * 128);
            uint32_t base = sb + SMEM_BUF_OFF + (uint32_t)((s % 3) * STG_SZ);
            uint32_t ad = base + pdst;
            uint32_t bd = base + STG_A + pdst;
            #pragma unroll
            for (int i = 0; i < 4; i++)      // A rows p = pr + 32*i  (y = i)
                CP16(ad + i * 4096, ga + (size_t)i * (WB * CIN));
            #pragma unroll
            for (int i = 0; i < 4; i++)      // B rows co = pr + 32*i
                CP16(bd + i * 4096, gb + (size_t)i * (32 * CIN));
        }
        CP_COMMIT();
    };

    // ---- consumer constants (8-bit m16n8k32 fragment mapping, from R3/R4) ----
    int mw = wid & 1;            // px half (64 px)
    int nw = wid >> 1;           // co quarter (32 co)
    int rlA = (lane & 7) + ((lane >> 3) & 1) * 8;
    int hiA = lane >> 4;
    int swA = rlA & 7;
    // B x4: lanes 0-7 -> (nt even, hi0), 8-15 -> (nt even, hi1),
    //       16-23 -> (nt odd, hi0), 24-31 -> (nt odd, hi1)
    int ntlB = lane >> 4;
    int hiB  = (lane >> 3) & 1;
    int rlB  = lane & 7;

    float acc[4][4][4];
    #pragma unroll
    for (int mt = 0; mt < 4; mt++)
        #pragma unroll
        for (int nt = 0; nt < 4; nt++)
            #pragma unroll
            for (int c = 0; c < 4; c++) acc[mt][nt][c] = 0.f;

    produce(0);
    produce(1);

    for (int s = 0; s < 18; s++) {
        CP_WAIT1();
        __syncthreads();           // stage s resident; all warps done with s-1
        produce(s + 2);            // refill buf (s+2)%3 == (s-1)%3

        uint32_t aB = sb + SMEM_BUF_OFF + (uint32_t)((s % 3) * STG_SZ);
        uint32_t bB = aB + STG_A;
        #pragma unroll
        for (int kc = 0; kc < 4; kc++) {       // 4 x k32 within 128 ci
            uint32_t a[4][4], b2[2][4];
            #pragma unroll
            for (int mt = 0; mt < 4; mt++) {
                uint32_t addr = aB + (uint32_t)((mw * 64 + mt * 16 + rlA) * 128)
                              + (uint32_t)((((kc * 2 + hiA) ^ swA) << 4));
                ldsm_x4(a[mt], addr);
            }
            #pragma unroll
            for (int np = 0; np < 2; np++) {
                int row = nw * 32 + (np * 2 + ntlB) * 8 + rlB;
                uint32_t addr = bB + (uint32_t)(row * 128)
                              + (uint32_t)((((kc * 2 + hiB) ^ rlB) << 4));
                ldsm_x4(b2[np], addr);
            }
            #pragma unroll
            for (int mt = 0; mt < 4; mt++)
                #pragma unroll
                for (int nt = 0; nt < 4; nt++)
                    mma_f8(acc[mt][nt], a[mt], &b2[nt >> 1][(nt & 1) * 2]);
        }
    }

    // ---- epilogue: transpose through smem, scale by alpha, coalesced stores
    __syncthreads();
    #pragma unroll
    for (int mt = 0; mt < 4; mt++) {
        int px = mw * 64 + mt * 16 + (lane >> 2);
        #pragma unroll
        for (int nt = 0; nt < 4; nt++) {
            int co = nw * 32 + nt * 8 + 2 * (lane & 3);
            epi[co * 132 + px]           = acc[mt][nt][0];
            epi[(co + 1) * 132 + px]     = acc[mt][nt][1];
            epi[co * 132 + px + 8]       = acc[mt][nt][2];
            epi[(co + 1) * 132 + px + 8] = acc[mt][nt][3];
        }
    }
    __syncthreads();

    int xg = x0 + lane;
    bool ok = (xg < W);
    #pragma unroll 4
    for (int r = wid; r < 512; r += 8) {
        int co = r >> 2, y = r & 3;
        float v = epi[co * 132 + y * 32 + lane] * alphaS[co];
        if (ok)
            out[(((size_t)n * COUT + co0 + co) * H + (y0 + y)) * W + xg] = v;
    }
}

// ---------------------------------------------------------------------------
extern "C" void kernel_launch(void* const* d_in, const int* in_sizes, int n_in,
                              void* d_out, int out_size) {
    const float* x     = (const float*)d_in[0];
    const float* M     = (const float*)d_in[1];
    const float* alpha = (const float*)d_in[2];
    float* out = (float*)d_out;

    void* gact_ptr = nullptr;
    cudaGetSymbolAddress(&gact_ptr, g_act);
    cudaMemsetAsync(gact_ptr, 0, (size_t)NB * HB * WB * CIN);

    {
        dim3 grid(2, 8, NB * H);
        dim3 block(32, 8);
        bin_act_kernel<<<grid, block>>>(x);
    }
    bin_w_kernel<<<(9 * COUT * CIN) / 256, 256>>>(M);

    cudaFuncSetAttribute(conv_mma_kernel,
                         cudaFuncAttributeMaxDynamicSharedMemorySize, SMEM_TOTAL);
    dim3 grid(28, NB, 2);
    conv_mma_kernel<<<grid, 256, SMEM_TOTAL>>>(alpha, out);
}

// round 7
// speedup vs baseline: 1.2280x; 1.2280x over previous
#include <cuda_runtime.h>
#include <cuda_bf16.h>
#include <cstdint>

// Problem constants
#define NB   32
#define CIN  256
#define COUT 256
#define H    56
#define W    56
#define HW   3136
#define HB   58   // padded rows (0..57)
#define WB   66   // padded cols (0..65)

// conv staging: stage covers 64 ci: A = 128px x 128B, B = 128co x 128B
#define STG_A   16384
#define STG_SZ  32768
#define NSTAGE  3
#define SMEM_EPI_OFF 1024
#define SMEM_BUF_OFF 1024
#define SMEM_TOTAL   (1024 + NSTAGE * STG_SZ)   // 99328

// Scratch (bf16 sign values)
__device__ __align__(1024) __nv_bfloat16 g_act[(size_t)NB * HB * WB * CIN];
__device__ __align__(1024) __nv_bfloat16 g_wb[9 * COUT * CIN];

__device__ __forceinline__ __nv_bfloat16 bsign(float v) {
    return __float2bfloat16((v > 0.f) ? 1.f : ((v < 0.f) ? -1.f : 0.f));
}

__device__ __forceinline__ uint32_t su32(const void* p) {
    return (uint32_t)__cvta_generic_to_shared(p);
}

#define CP16(dst, src) \
    asm volatile("cp.async.cg.shared.global [%0], [%1], 16;\n" :: "r"(dst), "l"(src))
#define CP_COMMIT() asm volatile("cp.async.commit_group;\n" ::: "memory")
#define CP_WAIT1()  asm volatile("cp.async.wait_group 1;\n" ::: "memory")

__device__ __forceinline__ void ldsm_x4(uint32_t* r, uint32_t addr) {
    asm volatile("ldmatrix.sync.aligned.m8n8.x4.shared.b16 {%0,%1,%2,%3}, [%4];"
                 : "=r"(r[0]), "=r"(r[1]), "=r"(r[2]), "=r"(r[3]) : "r"(addr));
}
__device__ __forceinline__ void mma_bf16(float* d, const uint32_t* a, const uint32_t* b) {
    asm volatile(
        "mma.sync.aligned.m16n8k16.row.col.f32.bf16.bf16.f32 "
        "{%0,%1,%2,%3}, {%4,%5,%6,%7}, {%8,%9}, {%0,%1,%2,%3};\n"
        : "+f"(d[0]), "+f"(d[1]), "+f"(d[2]), "+f"(d[3])
        : "r"(a[0]), "r"(a[1]), "r"(a[2]), "r"(a[3]), "r"(b[0]), "r"(b[1]));
}

// ---------------------------------------------------------------------------
// Zero only the padded borders of g_act (rows 0/57 full width; cols 0,57..65
// for rows 1..56). 692 border px per image; 512B (256 bf16) each.
// Each thread writes 16B; 32 threads per px.
// ---------------------------------------------------------------------------
__global__ void zero_border_kernel() {
    int idx = blockIdx.x * 256 + threadIdx.x;
    const int total = NB * 692 * 32;
    if (idx >= total) return;
    int word = idx & 31;              // 16B word within px
    int bp   = (idx >> 5) % 692;
    int n    = idx / (692 * 32);
    int yy, xx;
    if (bp < 66)       { yy = 0;  xx = bp; }
    else if (bp < 132) { yy = 57; xx = bp - 66; }
    else {
        int r = bp - 132;             // 0..559 -> rows 1..56, 10 cols
        yy = 1 + r / 10;
        int c = r % 10;
        xx = (c == 0) ? 0 : (56 + c); // 0, 57..65
    }
    float4* p = reinterpret_cast<float4*>(g_act);
    p[((size_t)(n * HB + yy) * WB + xx) * 32 + word] = make_float4(0.f, 0.f, 0.f, 0.f);
}

// ---------------------------------------------------------------------------
// Binarize + transpose x: NCHW fp32 -> padded NHWC bf16 (interior only).
// 32ci x 32x tiles via smem; packed u32 stores (2 ci per store).
// ---------------------------------------------------------------------------
__global__ void bin_act_kernel(const float* __restrict__ x) {
    __shared__ uint16_t t[32][33];
    int nz = blockIdx.z;
    int n = nz / H, y = nz % H;
    int x0 = blockIdx.x * 32;
    int c0 = blockIdx.y * 32;
    int tid = threadIdx.x + threadIdx.y * 32;
    int tx = threadIdx.x, ty = threadIdx.y;

    #pragma unroll
    for (int i = 0; i < 4; i++) {
        int ci = c0 + ty + i * 8;
        int xx = x0 + tx;
        float v = 0.f;
        if (xx < W)
            v = x[(((size_t)n * CIN + ci) * H + y) * W + xx];
        t[ty + i * 8][tx] = __bfloat16_as_ushort(bsign(v));
    }
    __syncthreads();
    // write phase: tid -> (px 0..15, ci-pair 0..15); 2 iterations of 16 px
    int pxi = tid >> 4;         // 0..15
    int cp  = tid & 15;         // ci pair
    #pragma unroll
    for (int j = 0; j < 2; j++) {
        int xl = pxi + j * 16;
        int xx = x0 + xl;
        if (xx < W) {
            uint32_t v = (uint32_t)t[cp * 2][xl] | ((uint32_t)t[cp * 2 + 1][xl] << 16);
            uint32_t* dst = reinterpret_cast<uint32_t*>(
                g_act + (((size_t)n * HB + (y + 1)) * WB + (xx + 1)) * CIN + c0);
            dst[cp] = v;
        }
    }
}

__global__ void bin_w_kernel(const float* __restrict__ M) {
    int o = blockIdx.x * 256 + threadIdx.x;
    int tap = o >> 16;
    int co  = (o >> 8) & 255;
    int ci  = o & 255;
    g_wb[o] = bsign(M[(size_t)(co * CIN + ci) * 9 + tap]);
}

// ---------------------------------------------------------------------------
// bf16 implicit-GEMM conv, linear-pixel tiling.
// CTA: 128 consecutive pixels (p = y*56+x) x 128 co; K = 9*256.
// 36 stages of 64 ci; 3-buffer cp.async pipeline; ldmatrix + mma.m16n8k16.bf16.
// ---------------------------------------------------------------------------
__global__ void __launch_bounds__(256, 2)
conv_mma_kernel(const float* __restrict__ alpha, float* __restrict__ out) {
    extern __shared__ char smem[];
    uint32_t sb = su32(smem);
    float* alphaS = (float*)smem;                 // 512B
    float* epi    = (float*)(smem + SMEM_EPI_OFF);

    int tid  = threadIdx.x;
    int wid  = tid >> 5, lane = tid & 31;
    int p0   = blockIdx.x * 128;                  // 0..24*128
    int n    = blockIdx.y;
    int co0  = blockIdx.z * 128;

    if (tid < 128) alphaS[tid] = alpha[co0 + tid];

    // ---- producer constants ----
    int pc = tid & 7;            // 16B chunk within 128B row (8 ci each)
    int pr = tid >> 3;           // smem row 0..31 (rows pr+32i, i=0..3)
    uint32_t pdst = (uint32_t)(pr * 128) + (uint32_t)(((pc ^ (pr & 7)) << 4));
    // per-row padded base offsets (tap (0,0) = padded (y, x))
    size_t aoff[4];
    #pragma unroll
    for (int i = 0; i < 4; i++) {
        int p = p0 + pr + 32 * i;
        if (p > HW - 1) p = HW - 1;   // clamp tail tile
        int yy = p / W, xx = p - yy * W;
        aoff[i] = ((size_t)(n * HB + yy) * WB + xx) * CIN + pc * 8;
    }
    const __nv_bfloat16* gbBase = g_wb + (size_t)(co0 + pr) * CIN + pc * 8;

    auto produce = [&](int s) {
        if (s < 36) {
            int tap = s >> 2, q = s & 3;        // 64-ci quarter
            int kh = tap / 3, kw = tap - kh * 3;
            int tapoff = (kh * WB + kw) * CIN + q * 64;
            const __nv_bfloat16* gb = gbBase + ((size_t)tap * (COUT * CIN) + q * 64);
            uint32_t base = sb + SMEM_BUF_OFF + (uint32_t)((s % 3) * STG_SZ);
            uint32_t ad = base + pdst;
            uint32_t bd = base + STG_A + pdst;
            #pragma unroll
            for (int i = 0; i < 4; i++)      // A rows p_loc = pr + 32*i
                CP16(ad + i * 4096, g_act + aoff[i] + tapoff);
            #pragma unroll
            for (int i = 0; i < 4; i++)      // B rows co = pr + 32*i
                CP16(bd + i * 4096, gb + (size_t)i * (32 * CIN));
        }
        CP_COMMIT();
    };

    // ---- consumer constants ----
    int mw = wid & 1;            // px half (64 px)
    int nw = wid >> 1;           // co quarter (32 co)
    int rlA = (lane & 7) + ((lane >> 3) & 1) * 8;
    int hiA = lane >> 4;
    int swA = rlA & 7;
    int rlB = (lane & 7) + ((lane >> 4) & 1) * 8;
    int hiB = (lane >> 3) & 1;
    int swB = rlB & 7;

    float acc[4][4][4];
    #pragma unroll
    for (int mt = 0; mt < 4; mt++)
        #pragma unroll
        for (int nt = 0; nt < 4; nt++)
            #pragma unroll
            for (int c = 0; c < 4; c++) acc[mt][nt][c] = 0.f;

    produce(0);
    produce(1);

    for (int s = 0; s < 36; s++) {
        CP_WAIT1();
        __syncthreads();           // stage s resident; all warps done with s-1
        produce(s + 2);            // refill buf (s+2)%3 == (s-1)%3

        uint32_t aB = sb + SMEM_BUF_OFF + (uint32_t)((s % 3) * STG_SZ);
        uint32_t bB = aB + STG_A;
        #pragma unroll
        for (int kc = 0; kc < 4; kc++) {       // 4 x k16 within 64 ci
            uint32_t a[4][4], b2[2][4];
            #pragma unroll
            for (int mt = 0; mt < 4; mt++) {
                uint32_t addr = aB + (uint32_t)((mw * 64 + mt * 16 + rlA) * 128)
                              + (uint32_t)((((kc * 2 + hiA) ^ swA) << 4));
                ldsm_x4(a[mt], addr);
            }
            #pragma unroll
            for (int np = 0; np < 2; np++) {   // 16 co each
                int row = nw * 32 + np * 16 + rlB;
                uint32_t addr = bB + (uint32_t)(row * 128)
                              + (uint32_t)((((kc * 2 + hiB) ^ swB) << 4));
                ldsm_x4(b2[np], addr);
            }
            #pragma unroll
            for (int mt = 0; mt < 4; mt++)
                #pragma unroll
                for (int nt = 0; nt < 4; nt++)
                    mma_bf16(acc[mt][nt], a[mt], &b2[nt >> 1][(nt & 1) * 2]);
        }
    }

    // ---- epilogue: transpose through smem, scale by alpha, coalesced stores
    __syncthreads();
    #pragma unroll
    for (int mt = 0; mt < 4; mt++) {
        int px = mw * 64 + mt * 16 + (lane >> 2);
        #pragma unroll
        for (int nt = 0; nt < 4; nt++) {
            int co = nw * 32 + nt * 8 + 2 * (lane & 3);
            epi[co * 132 + px]           = acc[mt][nt][0];
            epi[(co + 1) * 132 + px]     = acc[mt][nt][1];
            epi[co * 132 + px + 8]       = acc[mt][nt][2];
            epi[(co + 1) * 132 + px + 8] = acc[mt][nt][3];
        }
    }
    __syncthreads();

    #pragma unroll 4
    for (int r = wid; r < 512; r += 8) {
        int co = r >> 2;
        int pl = (r & 3) * 32 + lane;       // local px 0..127
        int p  = p0 + pl;
        if (p < HW) {
            float v = epi[co * 132 + pl] * alphaS[co];
            out[((size_t)n * COUT + co0 + co) * HW + p] = v;
        }
    }
}

// ---------------------------------------------------------------------------
extern "C" void kernel_launch(void* const* d_in, const int* in_sizes, int n_in,
                              void* d_out, int out_size) {
    const float* x     = (const float*)d_in[0];
    const float* M     = (const float*)d_in[1];
    const float* alpha = (const float*)d_in[2];
    float* out = (float*)d_out;

    {
        int total = NB * 692 * 32;
        zero_border_kernel<<<(total + 255) / 256, 256>>>();
    }
    {
        dim3 grid(2, 8, NB * H);
        dim3 block(32, 8);
        bin_act_kernel<<<grid, block>>>(x);
    }
    bin_w_kernel<<<(9 * COUT * CIN) / 256, 256>>>(M);

    cudaFuncSetAttribute(conv_mma_kernel,
                         cudaFuncAttributeMaxDynamicSharedMemorySize, SMEM_TOTAL);
    dim3 grid(25, NB, 2);   // 25 px-tiles of 128 (last half), 32 imgs, 2 co-halves
    conv_mma_kernel<<<grid, 256, SMEM_TOTAL>>>(alpha, out);
}